// round 1
// baseline (speedup 1.0000x reference)
#include <cuda_runtime.h>
#include <math.h>

#define KS 4
#define STRIDE 2
#define IMG 512
#define BS 32
#define OH 255
#define OW 255
#define PPI (OH * OW)           // patches per image = 65025
#define NPATCH (BS * PPI)       // 2,080,800
#define NOUT (BS * IMG * IMG)   // 8,388,608
#define EPS 1e-8f

// scratch: per-patch cosine similarity
__device__ float g_sim[NPATCH];

// Kernel A: one thread per patch. Gather 4x4 window, run MLP, cosine sim.
__global__ void sim_kernel(const float* __restrict__ img,
                           const float* __restrict__ W1, const float* __restrict__ b1,
                           const float* __restrict__ W2, const float* __restrict__ b2,
                           const float* __restrict__ W3, const float* __restrict__ b3) {
    // shared weight staging: W1(64) b1(4) W2(16) b2(4) W3(64) b3(16) = 168
    __shared__ float w[168];
    int t = threadIdx.x;
    if (t < 168) {
        float v;
        if (t < 64)        v = W1[t];
        else if (t < 68)   v = b1[t - 64];
        else if (t < 84)   v = W2[t - 68];
        else if (t < 88)   v = b2[t - 84];
        else if (t < 152)  v = W3[t - 88];
        else               v = b3[t - 152];
        w[t] = v;
    }
    __syncthreads();
    const float* sW1 = w;
    const float* sb1 = w + 64;
    const float* sW2 = w + 68;
    const float* sb2 = w + 84;
    const float* sW3 = w + 88;
    const float* sb3 = w + 152;

    int idx = blockIdx.x * blockDim.x + t;
    if (idx >= NPATCH) return;

    int b  = idx / PPI;
    int p  = idx - b * PPI;
    int oy = p / OW;
    int ox = p - oy * OW;

    const float* ip = img + ((size_t)b * IMG + (size_t)(STRIDE * oy)) * IMG + (STRIDE * ox);

    float x[16];
#pragma unroll
    for (int r = 0; r < 4; r++) {
#pragma unroll
        for (int c = 0; c < 4; c++) {
            x[r * 4 + c] = __ldg(ip + (size_t)r * IMG + c);
        }
    }

    // layer 1: 16 -> 4, relu
    float h1[4];
#pragma unroll
    for (int j = 0; j < 4; j++) h1[j] = sb1[j];
#pragma unroll
    for (int i = 0; i < 16; i++) {
#pragma unroll
        for (int j = 0; j < 4; j++) h1[j] = fmaf(x[i], sW1[i * 4 + j], h1[j]);
    }
#pragma unroll
    for (int j = 0; j < 4; j++) h1[j] = fmaxf(h1[j], 0.0f);

    // layer 2: 4 -> 4, relu
    float h2[4];
#pragma unroll
    for (int j = 0; j < 4; j++) h2[j] = sb2[j];
#pragma unroll
    for (int i = 0; i < 4; i++) {
#pragma unroll
        for (int j = 0; j < 4; j++) h2[j] = fmaf(h1[i], sW2[i * 4 + j], h2[j]);
    }
#pragma unroll
    for (int j = 0; j < 4; j++) h2[j] = fmaxf(h2[j], 0.0f);

    // layer 3: 4 -> 16, relu; fused cosine accumulation
    float dot = 0.0f, nx2 = 0.0f, ny2 = 0.0f;
#pragma unroll
    for (int i = 0; i < 16; i++) {
        float y = sb3[i];
#pragma unroll
        for (int j = 0; j < 4; j++) y = fmaf(h2[j], sW3[j * 16 + i], y);
        y = fmaxf(y, 0.0f);
        dot = fmaf(x[i], y, dot);
        nx2 = fmaf(x[i], x[i], nx2);
        ny2 = fmaf(y, y, ny2);
    }

    float nx = fmaxf(sqrtf(nx2), EPS);
    float ny = fmaxf(sqrtf(ny2), EPS);
    g_sim[idx] = dot / (nx * ny);
}

// Kernel B: gather-fold. Each output pixel averages the <=2x2 patches covering it.
__global__ void fold_kernel(float* __restrict__ out) {
    int idx = blockIdx.x * blockDim.x + threadIdx.x;
    if (idx >= NOUT) return;

    int b = idx >> 18;                 // / (512*512)
    int p = idx & (IMG * IMG - 1);
    int i = p >> 9;                    // row
    int j = p & (IMG - 1);             // col

    int oy0 = max(0, (i - 2) >> 1);
    int oy1 = min(OH - 1, i >> 1);
    int ox0 = max(0, (j - 2) >> 1);
    int ox1 = min(OW - 1, j >> 1);

    const float* simb = g_sim + (size_t)b * PPI;
    float acc = 0.0f;
    int cnt = 0;
    for (int oy = oy0; oy <= oy1; oy++) {
        for (int ox = ox0; ox <= ox1; ox++) {
            acc += __ldg(simb + oy * OW + ox);
            cnt++;
        }
    }
    out[idx] = acc / (float)cnt;
}

extern "C" void kernel_launch(void* const* d_in, const int* in_sizes, int n_in,
                              void* d_out, int out_size) {
    const float* img = (const float*)d_in[0];
    const float* W1  = (const float*)d_in[1];
    const float* b1  = (const float*)d_in[2];
    const float* W2  = (const float*)d_in[3];
    const float* b2  = (const float*)d_in[4];
    const float* W3  = (const float*)d_in[5];
    const float* b3  = (const float*)d_in[6];
    float* out = (float*)d_out;

    {
        int threads = 256;
        int blocks = (NPATCH + threads - 1) / threads;
        sim_kernel<<<blocks, threads>>>(img, W1, b1, W2, b2, W3, b3);
    }
    {
        int threads = 256;
        int blocks = (NOUT + threads - 1) / threads;
        fold_kernel<<<blocks, threads>>>(out);
    }
}

// round 2
// speedup vs baseline: 1.1994x; 1.1994x over previous
#include <cuda_runtime.h>
#include <math.h>

#define KS 4
#define STRIDE 2
#define IMG 512
#define BS 32
#define OH 255
#define OW 255
#define EPS 1e-8f

// Tiling: each block produces a 32x32 pixel output tile = 16x16 "cells"
// (a cell = 2x2 identical output pixels). Needs 17x17 patches, which need
// a 36x36 img halo tile.
#define TC 16                 // cells per block dim
#define NPATCH_T 17           // patches per block dim
#define TROWS 36              // img tile rows/cols
#define TSTRIDE 38            // padded smem row stride (even -> float2 aligned)

__global__ __launch_bounds__(256)
void fused_kernel(const float* __restrict__ img,
                  const float* __restrict__ W1, const float* __restrict__ b1,
                  const float* __restrict__ W2, const float* __restrict__ b2,
                  const float* __restrict__ W3, const float* __restrict__ b3,
                  float* __restrict__ out) {
    __shared__ float tile[TROWS * TSTRIDE];      // 36x38
    __shared__ float sim[NPATCH_T * 18];         // 17x18 (padded)
    __shared__ float w[168];                     // W1 b1 W2 b2 W3 b3

    const int t  = threadIdx.x;                  // 0..255
    const int b0 = blockIdx.x * TC;              // cell col origin
    const int a0 = blockIdx.y * TC;              // cell row origin
    const int bt = blockIdx.z;                   // batch

    // stage weights
    if (t < 168) {
        float v;
        if (t < 64)        v = W1[t];
        else if (t < 68)   v = b1[t - 64];
        else if (t < 84)   v = W2[t - 68];
        else if (t < 88)   v = b2[t - 84];
        else if (t < 152)  v = W3[t - 88];
        else               v = b3[t - 152];
        w[t] = v;
    }

    // load img halo tile: global rows 2*a0-2 .. 2*a0+33, cols 2*b0-2 .. 2*b0+33
    const int gr0 = 2 * a0 - 2;
    const int gc0 = 2 * b0 - 2;
    const float* imgb = img + (size_t)bt * IMG * IMG;
#pragma unroll
    for (int i = t; i < TROWS * TROWS; i += 256) {
        int r = i / TROWS;
        int c = i - r * TROWS;
        int gr = gr0 + r;
        int gc = gc0 + c;
        float v = 0.0f;
        if ((unsigned)gr < IMG && (unsigned)gc < IMG)
            v = __ldg(imgb + (size_t)gr * IMG + gc);
        tile[r * TSTRIDE + c] = v;
    }
    __syncthreads();

    const float* sW1 = w;
    const float* sb1 = w + 64;
    const float* sW2 = w + 68;
    const float* sb2 = w + 84;
    const float* sW3 = w + 88;
    const float* sb3 = w + 152;

    // compute 17x17 patches (2 rounds)
#pragma unroll
    for (int p = t; p < NPATCH_T * NPATCH_T; p += 256) {
        int py = p / NPATCH_T;
        int px = p - py * NPATCH_T;
        int oy = a0 - 1 + py;
        int ox = b0 - 1 + px;
        float s = 0.0f;
        if ((unsigned)oy < OH && (unsigned)ox < OW) {
            // gather 4x4 window from smem (float2 pairs, 8B aligned)
            float x[16];
            const float* base = tile + (2 * py) * TSTRIDE + 2 * px;
#pragma unroll
            for (int r = 0; r < 4; r++) {
                const float2* rp = reinterpret_cast<const float2*>(base + r * TSTRIDE);
                float2 v0 = rp[0];
                float2 v1 = rp[1];
                x[r * 4 + 0] = v0.x; x[r * 4 + 1] = v0.y;
                x[r * 4 + 2] = v1.x; x[r * 4 + 3] = v1.y;
            }

            // layer 1: 16 -> 4, relu
            float h1[4];
#pragma unroll
            for (int j = 0; j < 4; j++) h1[j] = sb1[j];
#pragma unroll
            for (int i = 0; i < 16; i++)
#pragma unroll
                for (int j = 0; j < 4; j++) h1[j] = fmaf(x[i], sW1[i * 4 + j], h1[j]);
#pragma unroll
            for (int j = 0; j < 4; j++) h1[j] = fmaxf(h1[j], 0.0f);

            // layer 2: 4 -> 4, relu
            float h2[4];
#pragma unroll
            for (int j = 0; j < 4; j++) h2[j] = sb2[j];
#pragma unroll
            for (int i = 0; i < 4; i++)
#pragma unroll
                for (int j = 0; j < 4; j++) h2[j] = fmaf(h1[i], sW2[i * 4 + j], h2[j]);
#pragma unroll
            for (int j = 0; j < 4; j++) h2[j] = fmaxf(h2[j], 0.0f);

            // layer 3: 4 -> 16, relu + fused cosine
            float dot = 0.0f, nx2 = 0.0f, ny2 = 0.0f;
#pragma unroll
            for (int i = 0; i < 16; i++) {
                float y = sb3[i];
#pragma unroll
                for (int j = 0; j < 4; j++) y = fmaf(h2[j], sW3[j * 16 + i], y);
                y = fmaxf(y, 0.0f);
                dot = fmaf(x[i], y, dot);
                nx2 = fmaf(x[i], x[i], nx2);
                ny2 = fmaf(y, y, ny2);
            }
            float nx = fmaxf(sqrtf(nx2), EPS);
            float ny = fmaxf(sqrtf(ny2), EPS);
            s = dot / (nx * ny);
        }
        sim[py * 18 + px] = s;
    }
    __syncthreads();

    // fold: each thread owns one cell (a, b) -> 2x2 identical output pixels
    const int tx = t & 15;
    const int ty = t >> 4;
    const int a = a0 + ty;
    const int b = b0 + tx;

    int oy0 = max(0, a - 1), oy1 = min(OH - 1, a);
    int ox0 = max(0, b - 1), ox1 = min(OW - 1, b);

    float acc = 0.0f;
    int cnt = 0;
    for (int oy = oy0; oy <= oy1; oy++) {
        int ly = oy - (a0 - 1);
        for (int ox = ox0; ox <= ox1; ox++) {
            int lx = ox - (b0 - 1);
            acc += sim[ly * 18 + lx];
            cnt++;
        }
    }
    float v = acc / (float)cnt;

    float2 vv = make_float2(v, v);
    float* ob = out + (size_t)bt * IMG * IMG + (size_t)(2 * a) * IMG + 2 * b;
    *reinterpret_cast<float2*>(ob) = vv;
    *reinterpret_cast<float2*>(ob + IMG) = vv;
}

extern "C" void kernel_launch(void* const* d_in, const int* in_sizes, int n_in,
                              void* d_out, int out_size) {
    const float* img = (const float*)d_in[0];
    const float* W1  = (const float*)d_in[1];
    const float* b1  = (const float*)d_in[2];
    const float* W2  = (const float*)d_in[3];
    const float* b2  = (const float*)d_in[4];
    const float* W3  = (const float*)d_in[5];
    const float* b3  = (const float*)d_in[6];
    float* out = (float*)d_out;

    dim3 grid(IMG / (2 * TC), IMG / (2 * TC), BS);   // 16 x 16 x 32
    fused_kernel<<<grid, 256>>>(img, W1, b1, W2, b2, W3, b3, out);
}

// round 3
// speedup vs baseline: 1.3333x; 1.1117x over previous
#include <cuda_runtime.h>
#include <math.h>

#define KS 4
#define STRIDE 2
#define IMG 512
#define BS 32
#define OH 255
#define OW 255
#define EPS2 1e-16f

// Tiling: each block produces a 32x32 pixel output tile = 16x16 "cells"
// (a cell = 2x2 identical output pixels). Needs 17x17 patches -> 36x36 img halo.
#define TC 16
#define NPATCH_T 17
#define TROWS 36
#define TSTRIDE 38

// Weights in constant memory: accessed via the uniform/constant port,
// keeping the shared-memory crossbar free for patch data.
__constant__ float cW1[64];
__constant__ float cb1[4];
__constant__ float cW2[16];
__constant__ float cb2[4];
__constant__ float cW3[64];
__constant__ float cb3[16];

__global__ __launch_bounds__(256)
void fused_kernel(const float* __restrict__ img, float* __restrict__ out) {
    __shared__ float tile[TROWS * TSTRIDE];   // 36x38 img halo
    __shared__ float sim[NPATCH_T * 18];      // 17x18 (padded)

    const int t  = threadIdx.x;
    const int b0 = blockIdx.x * TC;
    const int a0 = blockIdx.y * TC;
    const int bt = blockIdx.z;

    // load img halo tile: global rows 2*a0-2 .. 2*a0+33, cols 2*b0-2 .. 2*b0+33
    const int gr0 = 2 * a0 - 2;
    const int gc0 = 2 * b0 - 2;
    const float* imgb = img + (size_t)bt * IMG * IMG;
#pragma unroll
    for (int i = t; i < TROWS * TROWS; i += 256) {
        int r = i / TROWS;
        int c = i - r * TROWS;
        int gr = gr0 + r;
        int gc = gc0 + c;
        float v = 0.0f;
        if ((unsigned)gr < IMG && (unsigned)gc < IMG)
            v = __ldg(imgb + (size_t)gr * IMG + gc);
        tile[r * TSTRIDE + c] = v;
    }
    __syncthreads();

    // compute 17x17 patches (2 rounds of 256 threads)
#pragma unroll
    for (int p = t; p < NPATCH_T * NPATCH_T; p += 256) {
        int py = p / NPATCH_T;
        int px = p - py * NPATCH_T;
        int oy = a0 - 1 + py;
        int ox = b0 - 1 + px;
        float s = 0.0f;
        if ((unsigned)oy < OH && (unsigned)ox < OW) {
            float x[16];
            const float* base = tile + (2 * py) * TSTRIDE + 2 * px;
#pragma unroll
            for (int r = 0; r < 4; r++) {
                const float2* rp = reinterpret_cast<const float2*>(base + r * TSTRIDE);
                float2 v0 = rp[0];
                float2 v1 = rp[1];
                x[r * 4 + 0] = v0.x; x[r * 4 + 1] = v0.y;
                x[r * 4 + 2] = v1.x; x[r * 4 + 3] = v1.y;
            }

            // layer 1: 16 -> 4, relu
            float h1[4];
#pragma unroll
            for (int j = 0; j < 4; j++) h1[j] = cb1[j];
#pragma unroll
            for (int i = 0; i < 16; i++)
#pragma unroll
                for (int j = 0; j < 4; j++) h1[j] = fmaf(x[i], cW1[i * 4 + j], h1[j]);
#pragma unroll
            for (int j = 0; j < 4; j++) h1[j] = fmaxf(h1[j], 0.0f);

            // layer 2: 4 -> 4, relu
            float h2[4];
#pragma unroll
            for (int j = 0; j < 4; j++) h2[j] = cb2[j];
#pragma unroll
            for (int i = 0; i < 4; i++)
#pragma unroll
                for (int j = 0; j < 4; j++) h2[j] = fmaf(h1[i], cW2[i * 4 + j], h2[j]);
#pragma unroll
            for (int j = 0; j < 4; j++) h2[j] = fmaxf(h2[j], 0.0f);

            // layer 3: 4 -> 16, relu + fused cosine accumulation
            float dot = 0.0f, nx2 = 0.0f, ny2 = 0.0f;
#pragma unroll
            for (int i = 0; i < 16; i++) {
                float y = cb3[i];
#pragma unroll
                for (int j = 0; j < 4; j++) y = fmaf(h2[j], cW3[j * 16 + i], y);
                y = fmaxf(y, 0.0f);
                dot = fmaf(x[i], y, dot);
                nx2 = fmaf(x[i], x[i], nx2);
                ny2 = fmaf(y, y, ny2);
            }
            // max(sqrt(n2), 1e-8) == sqrt(max(n2, 1e-16)); rsqrt form avoids div
            s = dot * rsqrtf(fmaxf(nx2, EPS2)) * rsqrtf(fmaxf(ny2, EPS2));
        }
        sim[py * 18 + px] = s;
    }
    __syncthreads();

    // fold: each thread owns one cell -> 2x2 identical output pixels
    const int tx = t & 15;
    const int ty = t >> 4;
    const int a = a0 + ty;
    const int b = b0 + tx;

    int oy0 = max(0, a - 1), oy1 = min(OH - 1, a);
    int ox0 = max(0, b - 1), ox1 = min(OW - 1, b);

    float acc = 0.0f;
    int cnt = 0;
    for (int oy = oy0; oy <= oy1; oy++) {
        int ly = oy - (a0 - 1);
        for (int ox = ox0; ox <= ox1; ox++) {
            int lx = ox - (b0 - 1);
            acc += sim[ly * 18 + lx];
            cnt++;
        }
    }
    float v = acc / (float)cnt;

    float2 vv = make_float2(v, v);
    float* ob = out + (size_t)bt * IMG * IMG + (size_t)(2 * a) * IMG + 2 * b;
    *reinterpret_cast<float2*>(ob) = vv;
    *reinterpret_cast<float2*>(ob + IMG) = vv;
}

extern "C" void kernel_launch(void* const* d_in, const int* in_sizes, int n_in,
                              void* d_out, int out_size) {
    const float* img = (const float*)d_in[0];
    float* out = (float*)d_out;

    // stage weights into constant memory (graph-capturable D2D memcpy nodes)
    cudaMemcpyToSymbolAsync(cW1, d_in[1], 64 * sizeof(float), 0, cudaMemcpyDeviceToDevice);
    cudaMemcpyToSymbolAsync(cb1, d_in[2],  4 * sizeof(float), 0, cudaMemcpyDeviceToDevice);
    cudaMemcpyToSymbolAsync(cW2, d_in[3], 16 * sizeof(float), 0, cudaMemcpyDeviceToDevice);
    cudaMemcpyToSymbolAsync(cb2, d_in[4],  4 * sizeof(float), 0, cudaMemcpyDeviceToDevice);
    cudaMemcpyToSymbolAsync(cW3, d_in[5], 64 * sizeof(float), 0, cudaMemcpyDeviceToDevice);
    cudaMemcpyToSymbolAsync(cb3, d_in[6], 16 * sizeof(float), 0, cudaMemcpyDeviceToDevice);

    dim3 grid(IMG / (2 * TC), IMG / (2 * TC), BS);   // 16 x 16 x 32
    fused_kernel<<<grid, 256>>>(img, out);
}